// round 12
// baseline (speedup 1.0000x reference)
#include <cuda.h>
#include <cuda_runtime.h>
#include <cstdint>

// Equivariant linear: segments (u,i) = (64,1),(32,3),(16,5); in==out dim 240.
// R10 kernel with 32-row tiles -> smem 52.2KB -> 3 CTAs/SM (occupancy lever).
// Same per-row wavefront geometry; half the accumulators per lane.

typedef unsigned long long u64;

__device__ __forceinline__ u64 fma2(u64 a, u64 b, u64 c) {
    u64 d;
    asm("fma.rn.f32x2 %0, %1, %2, %3;" : "=l"(d) : "l"(a), "l"(b), "l"(c));
    return d;
}
__device__ __forceinline__ u64 dup2(float x) {
    u64 d;
    asm("mov.b64 %0, {%1, %2};" : "=l"(d) : "f"(x), "f"(x));
    return d;
}
__device__ __forceinline__ void unpack2(u64 v, float& a, float& b) {
    asm("mov.b64 {%0, %1}, %2;" : "=f"(a), "=f"(b) : "l"(v));
}
__device__ __forceinline__ uint32_t s2u(const void* p) {
    uint32_t a;
    asm("{ .reg .u64 t; cvta.to.shared.u64 t, %1; cvt.u32.u64 %0, t; }"
        : "=r"(a) : "l"(p));
    return a;
}
__device__ __forceinline__ void mbar_wait0(uint32_t mbar) {
    asm volatile(
        "{\n\t.reg .pred P;\n\t"
        "W%=:\n\t"
        "mbarrier.try_wait.parity.shared.b64 P, [%0], 0;\n\t"
        "@P bra.uni D%=;\n\t"
        "bra.uni W%=;\n\t"
        "D%=:\n\t}"
        :: "r"(mbar) : "memory");
}
__device__ __forceinline__ void tma_load2d(uint32_t dst, const CUtensorMap* m,
                                           int cx, int cy, uint32_t mbar) {
    asm volatile(
        "cp.async.bulk.tensor.2d.shared::cta.global.tile.mbarrier::complete_tx::bytes "
        "[%0], [%1, {%2, %3}], [%4];"
        :: "r"(dst), "l"(m), "r"(cx), "r"(cy), "r"(mbar) : "memory");
}
__device__ __forceinline__ void tma_store2d(const CUtensorMap* m, int cx, int cy,
                                            uint32_t src) {
    asm volatile(
        "cp.async.bulk.tensor.2d.global.shared::cta.tile.bulk_group "
        "[%0, {%1, %2}], [%3];"
        :: "l"(m), "r"(cx), "r"(cy), "r"(src) : "memory");
}

#define T0W 100
#define T1W 140
#define TROWS 32
#define SX0_OFF 5376
#define SX1_OFF (SX0_OFF + TROWS * T0W)      // 8576
#define MBAR_OFF (SX1_OFF + TROWS * T1W)     // 13056
#define SMEM_BYTES ((MBAR_OFF + 4) * 4)      // 52240

__global__ __launch_bounds__(256, 3) void eqlin_kernel(
    const __grid_constant__ CUtensorMap mi0,
    const __grid_constant__ CUtensorMap mi1,
    const __grid_constant__ CUtensorMap mo0,
    const __grid_constant__ CUtensorMap mo1,
    const float* __restrict__ w)
{
    extern __shared__ __align__(128) float sm[];
    float* sw  = sm;
    float* sx0 = sm + SX0_OFF;
    float* sx1 = sm + SX1_OFF;
    const uint32_t mbar = s2u(sm + MBAR_OFF);

    const int tid = threadIdx.x;
    const int row0 = blockIdx.x * TROWS;

    if (tid == 0)
        asm volatile("mbarrier.init.shared.b64 [%0], 1;" :: "r"(mbar) : "memory");
    __syncthreads();
    if (tid == 0) {
        asm volatile("mbarrier.arrive.expect_tx.shared.b64 _, [%0], 30720;"
                     :: "r"(mbar) : "memory");
        tma_load2d(s2u(sx0), &mi0, 0,   row0, mbar);
        tma_load2d(s2u(sx1), &mi1, 100, row0, mbar);
    }

    // ---- stage weights (overlaps TMA), pre-scaled, plain layout ----
    #pragma unroll
    for (int k = 0; k < 21; k++) {
        int idx = tid + k * 256;
        float s = (idx < 4096) ? 0.125f
                 : (idx < 5120) ? 0.17677669529663687f
                                : 0.25f;
        sw[idx] = w[idx] * s;
    }
    __syncthreads();
    mbar_wait0(mbar);

    const int warp = tid >> 5, lane = tid & 31;

    // ================= Segment 1: warp tile 8r x 32v ======================
    // warp: rg = warp>>1 (rows 8rg..8rg+7), vh = warp&1 (v half)
    // lane: lv = lane&7 (v0 = 32vh+4lv), lr = lane>>3; rows 8rg+lr, 8rg+lr+4
    {
        const int rg = warp >> 1, vh = warp & 1;
        const int lv = lane & 7, lr = lane >> 3;
        const int v0 = 32 * vh + 4 * lv;
        const ulonglong2* w1p = (const ulonglong2*)sw;
        const float* xb = sx0 + (8 * rg + lr) * T0W;

        u64 aA0 = 0, aB0 = 0, aA1 = 0, aB1 = 0;

        #pragma unroll 4
        for (int k4 = 0; k4 < 16; k4++) {
            float4 x0 = *(const float4*)(xb + 4 * k4);
            float4 x1 = *(const float4*)(xb + 4 * T0W + 4 * k4);
            #pragma unroll
            for (int uu = 0; uu < 4; uu++) {
                ulonglong2 wp = w1p[(4 * k4 + uu) * 16 + 8 * vh + lv];
                float e0 = (uu == 0) ? x0.x : (uu == 1) ? x0.y : (uu == 2) ? x0.z : x0.w;
                float e1 = (uu == 0) ? x1.x : (uu == 1) ? x1.y : (uu == 2) ? x1.z : x1.w;
                u64 d0 = dup2(e0), d1 = dup2(e1);
                aA0 = fma2(d0, wp.x, aA0);  aB0 = fma2(d0, wp.y, aB0);
                aA1 = fma2(d1, wp.x, aA1);  aB1 = fma2(d1, wp.y, aB1);
            }
        }
        __syncthreads();   // all seg1 reads (cols 0-63) done everywhere
        float* pb = sx0 + (8 * rg + lr) * T0W + v0;
        {
            float4 o; unpack2(aA0, o.x, o.y); unpack2(aB0, o.z, o.w);
            *(float4*)(pb) = o;
        }
        {
            float4 o; unpack2(aA1, o.x, o.y); unpack2(aB1, o.z, o.w);
            *(float4*)(pb + 4 * T0W) = o;
        }
    }

    // ================= Segment 2: 2 rows/thread, v-pair ====================
    // ty = tid>>4 (rows ty, ty+16), tx = tid&15 (v-pair 2tx)
    {
        const int ty = tid >> 4, tx = tid & 15;
        const u64* w2p = (const u64*)(sw + 4096);
        u64 a20 = 0, a21 = 0, a22 = 0;      // row ty
        u64 b20 = 0, b21 = 0, b22 = 0;      // row ty+16

        #pragma unroll
        for (int k4 = 0; k4 < 8; k4++) {    // k4 0-2: sx0 (cols 64-99); 3-7: sx1
            u64 wp0 = w2p[(4 * k4 + 0) * 16 + tx];
            u64 wp1 = w2p[(4 * k4 + 1) * 16 + tx];
            u64 wp2 = w2p[(4 * k4 + 2) * 16 + tx];
            u64 wp3 = w2p[(4 * k4 + 3) * 16 + tx];
            const float* ba = (k4 < 3) ? (sx0 + ty * T0W + 64 + 12 * k4)
                                       : (sx1 + ty * T1W + 12 * k4 - 36);
            const float* bb = (k4 < 3) ? (sx0 + (ty + 16) * T0W + 64 + 12 * k4)
                                       : (sx1 + (ty + 16) * T1W + 12 * k4 - 36);
            float4 qa0 = *(const float4*)(ba);
            float4 qa1 = *(const float4*)(ba + 4);
            float4 qa2 = *(const float4*)(ba + 8);
            float4 qb0 = *(const float4*)(bb);
            float4 qb1 = *(const float4*)(bb + 4);
            float4 qb2 = *(const float4*)(bb + 8);
            a20 = fma2(dup2(qa0.x), wp0, a20);  b20 = fma2(dup2(qb0.x), wp0, b20);
            a21 = fma2(dup2(qa0.y), wp0, a21);  b21 = fma2(dup2(qb0.y), wp0, b21);
            a22 = fma2(dup2(qa0.z), wp0, a22);  b22 = fma2(dup2(qb0.z), wp0, b22);
            a20 = fma2(dup2(qa0.w), wp1, a20);  b20 = fma2(dup2(qb0.w), wp1, b20);
            a21 = fma2(dup2(qa1.x), wp1, a21);  b21 = fma2(dup2(qb1.x), wp1, b21);
            a22 = fma2(dup2(qa1.y), wp1, a22);  b22 = fma2(dup2(qb1.y), wp1, b22);
            a20 = fma2(dup2(qa1.z), wp2, a20);  b20 = fma2(dup2(qb1.z), wp2, b20);
            a21 = fma2(dup2(qa1.w), wp2, a21);  b21 = fma2(dup2(qb1.w), wp2, b21);
            a22 = fma2(dup2(qa2.x), wp2, a22);  b22 = fma2(dup2(qb2.x), wp2, b22);
            a20 = fma2(dup2(qa2.y), wp3, a20);  b20 = fma2(dup2(qb2.y), wp3, b20);
            a21 = fma2(dup2(qa2.z), wp3, a21);  b21 = fma2(dup2(qb2.z), wp3, b21);
            a22 = fma2(dup2(qa2.w), wp3, a22);  b22 = fma2(dup2(qb2.w), wp3, b22);
        }
        __syncthreads();   // all seg2 reads (cols 64-159) done everywhere
        {
            float* p = (tx < 6) ? (sx0 + ty * T0W + 64 + 6 * tx)
                                : (sx1 + ty * T1W + 6 * tx - 36);
            float l0, h0, l1, h1, l2, h2;
            unpack2(a20, l0, h0); unpack2(a21, l1, h1); unpack2(a22, l2, h2);
            *(float2*)(p)     = make_float2(l0, l1);
            *(float2*)(p + 2) = make_float2(l2, h0);
            *(float2*)(p + 4) = make_float2(h1, h2);
        }
        {
            float* p = (tx < 6) ? (sx0 + (ty + 16) * T0W + 64 + 6 * tx)
                                : (sx1 + (ty + 16) * T1W + 6 * tx - 36);
            float l0, h0, l1, h1, l2, h2;
            unpack2(b20, l0, h0); unpack2(b21, l1, h1); unpack2(b22, l2, h2);
            *(float2*)(p)     = make_float2(l0, l1);
            *(float2*)(p + 2) = make_float2(l2, h0);
            *(float2*)(p + 4) = make_float2(h1, h2);
        }
    }

    // ================= Segment 3: warp tile 4r x 16v, v-pairs ===============
    // lane: lv3 = lane&7 (v-pair 2lv3), lr3 = lane>>3; row = 4warp + lr3
    {
        const int lv3 = lane & 7, lr3 = lane >> 3;
        const int row = 4 * warp + lr3;
        const u64* w3q = (const u64*)(sw + 5120);  // pair idx u*8+lv3
        u64 c0 = 0, c1 = 0, c2 = 0, c3 = 0, c4 = 0;

        #pragma unroll
        for (int k4 = 0; k4 < 4; k4++) {
            const float* pa = sx1 + row * T1W + 60 + 20 * k4;
            float4 q0 = *(const float4*)(pa);
            float4 q1 = *(const float4*)(pa + 4);
            float4 q2 = *(const float4*)(pa + 8);
            float4 q3 = *(const float4*)(pa + 12);
            float4 q4 = *(const float4*)(pa + 16);
            u64 wu0 = w3q[(4 * k4 + 0) * 8 + lv3];
            u64 wu1 = w3q[(4 * k4 + 1) * 8 + lv3];
            u64 wu2 = w3q[(4 * k4 + 2) * 8 + lv3];
            u64 wu3 = w3q[(4 * k4 + 3) * 8 + lv3];
            c0 = fma2(dup2(q0.x), wu0, c0);
            c1 = fma2(dup2(q0.y), wu0, c1);
            c2 = fma2(dup2(q0.z), wu0, c2);
            c3 = fma2(dup2(q0.w), wu0, c3);
            c4 = fma2(dup2(q1.x), wu0, c4);
            c0 = fma2(dup2(q1.y), wu1, c0);
            c1 = fma2(dup2(q1.z), wu1, c1);
            c2 = fma2(dup2(q1.w), wu1, c2);
            c3 = fma2(dup2(q2.x), wu1, c3);
            c4 = fma2(dup2(q2.y), wu1, c4);
            c0 = fma2(dup2(q2.z), wu2, c0);
            c1 = fma2(dup2(q2.w), wu2, c1);
            c2 = fma2(dup2(q3.x), wu2, c2);
            c3 = fma2(dup2(q3.y), wu2, c3);
            c4 = fma2(dup2(q3.z), wu2, c4);
            c0 = fma2(dup2(q3.w), wu3, c0);
            c1 = fma2(dup2(q4.x), wu3, c1);
            c2 = fma2(dup2(q4.y), wu3, c2);
            c3 = fma2(dup2(q4.z), wu3, c3);
            c4 = fma2(dup2(q4.w), wu3, c4);
        }
        __syncthreads();   // all seg3 reads done everywhere
        float* pA = sx1 + row * T1W + 60 + 10 * lv3;
        float l0, h0, l1, h1, l2, h2, l3, h3, l4, h4;
        unpack2(c0, l0, h0); unpack2(c1, l1, h1); unpack2(c2, l2, h2);
        unpack2(c3, l3, h3); unpack2(c4, l4, h4);
        *(float2*)(pA)     = make_float2(l0, l1);
        *(float2*)(pA + 2) = make_float2(l2, l3);
        *(float2*)(pA + 4) = make_float2(l4, h0);
        *(float2*)(pA + 6) = make_float2(h1, h2);
        *(float2*)(pA + 8) = make_float2(h3, h4);
    }

    __syncthreads();
    if (tid == 0) {
        asm volatile("fence.proxy.async;" ::: "memory");
        tma_store2d(&mo0, 0,   row0, s2u(sx0));
        tma_store2d(&mo1, 100, row0, s2u(sx1));
        asm volatile("cp.async.bulk.commit_group;" ::: "memory");
        asm volatile("cp.async.bulk.wait_group 0;" ::: "memory");
    }
}

// ===================== host side =====================

typedef CUresult (*TmapEncodeFn)(
    CUtensorMap*, CUtensorMapDataType, cuuint32_t, void*,
    const cuuint64_t*, const cuuint64_t*, const cuuint32_t*, const cuuint32_t*,
    CUtensorMapInterleave, CUtensorMapSwizzle, CUtensorMapL2promotion,
    CUtensorMapFloatOOBfill);

static void enc_map(TmapEncodeFn f, CUtensorMap* m, void* base, long long n,
                    uint32_t boxw) {
    cuuint64_t dims[2]    = {240, (cuuint64_t)n};
    cuuint64_t strides[1] = {240 * 4};
    cuuint32_t box[2]     = {boxw, TROWS};
    cuuint32_t es[2]      = {1, 1};
    f(m, CU_TENSOR_MAP_DATA_TYPE_FLOAT32, 2, base, dims, strides, box, es,
      CU_TENSOR_MAP_INTERLEAVE_NONE, CU_TENSOR_MAP_SWIZZLE_NONE,
      CU_TENSOR_MAP_L2_PROMOTION_L2_128B, CU_TENSOR_MAP_FLOAT_OOB_FILL_NONE);
}

extern "C" void kernel_launch(void* const* d_in, const int* in_sizes, int n_in,
                              void* d_out, int out_size) {
    void* x = d_in[0];
    const float* w = (const float*)d_in[1];
    const long long n = in_sizes[0] / 240;          // 200000
    const int blocks = (int)((n + TROWS - 1) / TROWS);   // 6250

    void* fp = nullptr;
    cudaDriverEntryPointQueryResult qr;
#if CUDART_VERSION >= 12050
    cudaGetDriverEntryPointByVersion("cuTensorMapEncodeTiled", &fp, 12000,
                                     cudaEnableDefault, &qr);
#else
    cudaGetDriverEntryPoint("cuTensorMapEncodeTiled", &fp, cudaEnableDefault, &qr);
#endif
    TmapEncodeFn enc = (TmapEncodeFn)fp;

    CUtensorMap mi0, mi1, mo0, mo1;
    enc_map(enc, &mi0, x, n, 100);
    enc_map(enc, &mi1, x, n, 140);
    enc_map(enc, &mo0, d_out, n, 100);
    enc_map(enc, &mo1, d_out, n, 140);

    static bool attr_set = false;
    if (!attr_set) {
        cudaFuncSetAttribute(eqlin_kernel,
                             cudaFuncAttributeMaxDynamicSharedMemorySize, SMEM_BYTES);
        attr_set = true;
    }
    eqlin_kernel<<<blocks, 256, SMEM_BYTES>>>(mi0, mi1, mo0, mo1, w);
}